// round 15
// baseline (speedup 1.0000x reference)
#include <cuda_runtime.h>

#define D     1024
#define HD    4096
#define LNUM  12
#define VOCAB 50257
#define NT    256
#define NW    8

// ---------------- global scratch ----------------
__device__ float g_x[D];
__device__ float g_k[D];
__device__ float g_v[D];
__device__ float g_r[D];
__device__ float g_k2[HD];
__device__ float g_r2[D];

// ---------------- 2-level software grid barrier ----------------
__device__ unsigned g_bar_gen = 0;
__device__ unsigned g_leaf[8 * 128];
__device__ unsigned g_root = 0;

__device__ __forceinline__ void grid_barrier(int nb) {
    __syncthreads();
    if (threadIdx.x == 0) {
        __threadfence();
        unsigned gen = *((volatile unsigned*)&g_bar_gen);
        int leaf = blockIdx.x & 7;
        unsigned target = (unsigned)((nb >> 3) + ((blockIdx.x & 7) < (nb & 7) ? 1 : 0));
        if (atomicAdd(&g_leaf[leaf * 128], 1u) == target - 1u) {
            g_leaf[leaf * 128] = 0;
            __threadfence();
            if (atomicAdd(&g_root, 1u) == 7u) {
                g_root = 0;
                __threadfence();
                atomicAdd(&g_bar_gen, 1u);
            }
        }
        while (*((volatile unsigned*)&g_bar_gen) == gen) { }
        __threadfence();
    }
    __syncthreads();
}

// ---------------- block-wide sum (8 warps) ----------------
__device__ __forceinline__ float block_sum(float v, float* sred) {
    int lane = threadIdx.x & 31, wid = threadIdx.x >> 5;
    #pragma unroll
    for (int o = 16; o; o >>= 1) v += __shfl_xor_sync(0xffffffffu, v, o);
    if (lane == 0) sred[wid] = v;
    __syncthreads();
    float t = 0.f;
    if (wid == 0) {
        t = (lane < NW) ? sred[lane] : 0.f;
        #pragma unroll
        for (int o = NW / 2; o; o >>= 1) t += __shfl_xor_sync(0xffffffffu, t, o);
        if (lane == 0) sred[0] = t;
    }
    __syncthreads();
    float r = sred[0];
    __syncthreads();
    return r;
}

// ---------------- pipelined item stream ----------------
// Items of 1024 floats (8 x LDG.128/lane). Double-buffered: while item i is
// consumed, item i+1's 8 loads are in flight. CL consecutive items form one
// logical row (accumulated before reduce+fin). Requires register headroom —
// NT=256 with no min-blocks so ptxas has up to 255 regs/thread.
template<class RowP, class VecP, class Fin>
__device__ __forceinline__ void pipe_run(int NR, int CL, int gw, int nwG, int lane,
                                         RowP rowp, VecP vecp, Fin fin) {
    int n = (gw < NR) ? (NR - 1 - gw * CL >= 0 ? 0 : 0) : 0; // placeholder; computed below
    (void)n;
    // total items for this warp: indices i = 0.. ; item i maps to global item gi = gw*CL? 
    // Simpler: global item id q = gw + j*nwG over item-space of size NR*CL? 
    // We use: item space = NR*CL items; warp owns consecutive CL-groups: rows gw, gw+nwG, ...
    // item j within row r: load rowp(r, j), vec vecp(r, j).
    // Implemented as flat loop below.
    float4 A[8], B[8];
    int r0 = gw;
    if (r0 >= NR) return;
    {
        const float4* p = (const float4*)rowp(r0, 0);
        #pragma unroll
        for (int u = 0; u < 8; u++) A[u] = __ldg(p + u * 32 + lane);
    }
    float s0 = 0.f, s1 = 0.f, s2 = 0.f, s3 = 0.f;
    for (int r = r0; r < NR; r += nwG) {
        for (int c = 0; c < CL; c++) {
            // prefetch next item
            int nr = r, nch = c + 1;
            if (nch == CL) { nr = r + nwG; nch = 0; }
            if (nr < NR) {
                const float4* p = (const float4*)rowp(nr, nch);
                #pragma unroll
                for (int u = 0; u < 8; u++) B[u] = __ldg(p + u * 32 + lane);
            }
            const float4* v4 = (const float4*)vecp(r, c);
            #pragma unroll
            for (int u = 0; u < 8; u++) {
                float4 b = v4[u * 32 + lane];
                s0 = fmaf(A[u].x, b.x, s0); s1 = fmaf(A[u].y, b.y, s1);
                s2 = fmaf(A[u].z, b.z, s2); s3 = fmaf(A[u].w, b.w, s3);
            }
            if (c == CL - 1) {
                float t = (s0 + s1) + (s2 + s3);
                #pragma unroll
                for (int o = 16; o; o >>= 1) t += __shfl_xor_sync(0xffffffffu, t, o);
                fin(r, t);
                s0 = s1 = s2 = s3 = 0.f;
            }
            #pragma unroll
            for (int u = 0; u < 8; u++) A[u] = B[u];
        }
    }
}

__global__ __launch_bounds__(NT) void rwkv_persistent(
    const int*   __restrict__ ctx,
    const float* __restrict__ st_in,
    const float* __restrict__ emb,
    const float* __restrict__ ln0,
    const float* __restrict__ ln1,
    const float* __restrict__ ln2,
    const float* __restrict__ lnout,
    const float* __restrict__ tmk,
    const float* __restrict__ tmv,
    const float* __restrict__ tmr,
    const float* __restrict__ tfirst,
    const float* __restrict__ tdecay,
    const float* __restrict__ kw,
    const float* __restrict__ vw,
    const float* __restrict__ rw,
    const float* __restrict__ ow,
    const float* __restrict__ ftmk,
    const float* __restrict__ ftmr,
    const float* __restrict__ fkw,
    const float* __restrict__ fvw,
    const float* __restrict__ frw,
    const float* __restrict__ head,
    float* __restrict__ out,
    int nb)
{
    __shared__ float sbuf[4096];
    __shared__ float sred[NW];

    const int tid  = threadIdx.x;
    const int lane = tid & 31;
    const int gw   = blockIdx.x * NW + (tid >> 5);
    const int nwG  = nb * NW;

    float* out_logits = out;
    float* out_state  = out + VOCAB;
    const float4* sb4 = (const float4*)sbuf;

    // ---------- stage 0 ----------
    if (blockIdx.x == 0) {
        const float* e = emb + (size_t)ctx[0] * D;
        float ss = 0.f;
        for (int j = tid; j < D; j += NT) { float t = e[j]; ss += t * t; }
        ss = block_sum(ss, sred);
        float inv = rsqrtf(ss * (1.f / D) + 1e-5f);
        for (int j = tid; j < D; j += NT) g_x[j] = e[j] * inv * ln0[j];
    }
    grid_barrier(nb);

    for (int l = 0; l < LNUM; l++) {
        const float* st_l  = st_in     + (size_t)l * 5 * D;
        float*       ost_l = out_state + (size_t)l * 5 * D;
        const float* kwl  = kw  + (size_t)l * D * D;
        const float* vwl  = vw  + (size_t)l * D * D;
        const float* rwl  = rw  + (size_t)l * D * D;
        const float* owl  = ow  + (size_t)l * D * D;
        const float* fkwl = fkw + (size_t)l * HD * D;
        const float* frwl = frw + (size_t)l * D * D;
        const float* fvwl = fvw + (size_t)l * D * HD;

        // ---------- stage A ----------
        {
            float ss = 0.f;
            for (int j = tid; j < D; j += NT) { float t = g_x[j]; ss += t * t; }
            ss = block_sum(ss, sred);
            float inv = rsqrtf(ss * (1.f / D) + 1e-5f);
            const float* l1 = ln1 + l * D;
            const float* mk = tmk + l * D;
            const float* mv = tmv + l * D;
            const float* mr = tmr + l * D;
            for (int j = tid; j < D; j += NT) {
                float xxj = g_x[j] * inv * l1[j];
                float sa  = st_l[D + j];
                float a_ = mk[j]; sbuf[j]         = xxj * a_ + sa * (1.f - a_);
                float b_ = mv[j]; sbuf[D + j]     = xxj * b_ + sa * (1.f - b_);
                float c_ = mr[j]; sbuf[2 * D + j] = xxj * c_ + sa * (1.f - c_);
                if (blockIdx.x == 0) ost_l[D + j] = xxj;
            }
            __syncthreads();
            pipe_run(3 * D, 1, gw, nwG, lane,
                [&](int r, int c) {
                    (void)c;
                    int m = r >> 10, rr = r & 1023;
                    const float* base = (m == 0) ? kwl : ((m == 1) ? vwl : rwl);
                    return base + (size_t)rr * D;
                },
                [&](int r, int c) { (void)c; return sb4 + (r >> 10) * 256; },
                [&](int r, float t) {
                    if (lane == 0) {
                        int m = r >> 10, rr = r & 1023;
                        if (m == 0)      g_k[rr] = t;
                        else if (m == 1) g_v[rr] = t;
                        else             g_r[rr] = t;
                    }
                });
        }
        grid_barrier(nb);

        // ---------- stage B ----------
        {
            const float* tfl = tfirst + l * D;
            const float* tdl = tdecay + l * D;
            for (int j = tid; j < D; j += NT) {
                float k  = g_k[j], v = g_v[j], rr = g_r[j];
                float aa = st_l[2 * D + j], bb = st_l[3 * D + j], pp = st_l[4 * D + j];
                float ww = tfl[j] + k;
                float p  = fmaxf(pp, ww);
                float e1 = __expf(pp - p), e2 = __expf(ww - p);
                float a  = e1 * aa + e2 * v;
                float b  = e1 * bb + e2;
                float sr = 1.f / (1.f + __expf(-rr));
                sbuf[j] = sr * (a / b);
                if (blockIdx.x == 0) {
                    float ww2 = pp + tdl[j];
                    float p2  = fmaxf(ww2, k);
                    float e1b = __expf(ww2 - p2), e2b = __expf(k - p2);
                    ost_l[2 * D + j] = e1b * aa + e2b * v;
                    ost_l[3 * D + j] = e1b * bb + e2b;
                    ost_l[4 * D + j] = p2;
                }
            }
            __syncthreads();
            pipe_run(D, 1, gw, nwG, lane,
                [&](int r, int c) { (void)c; return owl + (size_t)r * D; },
                [&](int r, int c) { (void)r; (void)c; return sb4; },
                [&](int r, float t) { if (lane == 0) g_x[r] += t; });
        }
        grid_barrier(nb);

        // ---------- stage C ----------
        {
            float ss = 0.f;
            for (int j = tid; j < D; j += NT) { float t = g_x[j]; ss += t * t; }
            ss = block_sum(ss, sred);
            float inv = rsqrtf(ss * (1.f / D) + 1e-5f);
            const float* l2l = ln2  + l * D;
            const float* fmk = ftmk + l * D;
            const float* fmr = ftmr + l * D;
            for (int j = tid; j < D; j += NT) {
                float yyj = g_x[j] * inv * l2l[j];
                float ff  = st_l[j];
                float a_ = fmk[j]; sbuf[j]     = yyj * a_ + ff * (1.f - a_);
                float b_ = fmr[j]; sbuf[D + j] = yyj * b_ + ff * (1.f - b_);
                if (blockIdx.x == 0) ost_l[j] = yyj;
            }
            __syncthreads();
            pipe_run(HD + D, 1, gw, nwG, lane,
                [&](int r, int c) {
                    (void)c;
                    return (r < HD) ? fkwl + (size_t)r * D
                                    : frwl + (size_t)(r - HD) * D;
                },
                [&](int r, int c) { (void)c; return (r < HD) ? sb4 : (sb4 + 256); },
                [&](int r, float t) {
                    if (lane == 0) {
                        if (r < HD) { t = fmaxf(t, 0.f); g_k2[r] = t * t; }
                        else        g_r2[r - HD] = t;
                    }
                });
        }
        grid_barrier(nb);

        // ---------- stage D (CL=4 chunks per 16KB row) ----------
        {
            for (int j = tid; j < HD; j += NT) sbuf[j] = g_k2[j];
            __syncthreads();
            const float sc = ((l + 1) % 6 == 0) ? 0.5f : 1.0f;
            pipe_run(D, 4, gw, nwG, lane,
                [&](int r, int c) { return fvwl + (size_t)r * HD + (size_t)c * 1024; },
                [&](int r, int c) { (void)r; return sb4 + c * 256; },
                [&](int r, float t) {
                    if (lane == 0) {
                        float sr = 1.f / (1.f + __expf(-g_r2[r]));
                        g_x[r] = (g_x[r] + sr * t) * sc;
                    }
                });
        }
        grid_barrier(nb);
    }

    // ---------- head ----------
    {
        float ss = 0.f;
        for (int j = tid; j < D; j += NT) { float t = g_x[j]; ss += t * t; }
        ss = block_sum(ss, sred);
        float inv = rsqrtf(ss * (1.f / D) + 1e-5f);
        for (int j = tid; j < D; j += NT) sbuf[j] = g_x[j] * inv * lnout[j];
        __syncthreads();
        pipe_run(VOCAB, 1, gw, nwG, lane,
            [&](int r, int c) { (void)c; return head + (size_t)r * D; },
            [&](int r, int c) { (void)r; (void)c; return sb4; },
            [&](int r, float t) { if (lane == 0) out_logits[r] = t; });
    }
}

extern "C" void kernel_launch(void* const* d_in, const int* in_sizes, int n_in,
                              void* d_out, int out_size) {
    (void)in_sizes; (void)n_in; (void)out_size;
    int nb = 0;
    cudaDeviceGetAttribute(&nb, cudaDevAttrMultiProcessorCount, 0);
    if (nb <= 0) nb = 148;
    if (nb > 1024) nb = 1024;

    rwkv_persistent<<<nb, NT>>>(
        (const int*)  d_in[0],   // ctx
        (const float*)d_in[1],   // state
        (const float*)d_in[2],   // emb
        (const float*)d_in[3],   // ln0_w
        (const float*)d_in[4],   // ln1_w
        (const float*)d_in[5],   // ln2_w
        (const float*)d_in[6],   // lnout_w
        (const float*)d_in[7],   // att_tmk
        (const float*)d_in[8],   // att_tmv
        (const float*)d_in[9],   // att_tmr
        (const float*)d_in[10],  // att_tfirst
        (const float*)d_in[11],  // att_tdecay
        (const float*)d_in[12],  // att_kw
        (const float*)d_in[13],  // att_vw
        (const float*)d_in[14],  // att_rw
        (const float*)d_in[15],  // att_ow
        (const float*)d_in[16],  // ffn_tmk
        (const float*)d_in[17],  // ffn_tmr
        (const float*)d_in[18],  // ffn_kw
        (const float*)d_in[19],  // ffn_vw
        (const float*)d_in[20],  // ffn_rw
        (const float*)d_in[21],  // head
        (float*)d_out, nb);
}

// round 16
// speedup vs baseline: 1.2266x; 1.2266x over previous
#include <cuda_runtime.h>

#define D     1024
#define HD    4096
#define LNUM  12
#define VOCAB 50257
#define NT    512
#define NW    16

// ---------------- global scratch ----------------
__device__ float g_xb[2][D];       // ping-pong residual stream
__device__ float g_k[D];
__device__ float g_v[D];
__device__ float g_r[D];
__device__ float g_k2[HD];
__device__ float g_r2[D];
__device__ float g_accD[D];        // fvw partials

// ---------------- 2-level software grid barrier ----------------
__device__ unsigned g_bar_gen = 0;
__device__ unsigned g_leaf[8 * 128];
__device__ unsigned g_root = 0;

__device__ __forceinline__ void grid_barrier(int nb) {
    __syncthreads();
    if (threadIdx.x == 0) {
        __threadfence();
        unsigned gen = *((volatile unsigned*)&g_bar_gen);
        int leaf = blockIdx.x & 7;
        unsigned target = (unsigned)((nb >> 3) + ((blockIdx.x & 7) < (nb & 7) ? 1 : 0));
        if (atomicAdd(&g_leaf[leaf * 128], 1u) == target - 1u) {
            g_leaf[leaf * 128] = 0;
            __threadfence();
            if (atomicAdd(&g_root, 1u) == 7u) {
                g_root = 0;
                __threadfence();
                atomicAdd(&g_bar_gen, 1u);
            }
        }
        while (*((volatile unsigned*)&g_bar_gen) == gen) { }
        __threadfence();
    }
    __syncthreads();
}

// ---------------- block-wide sum ----------------
__device__ __forceinline__ float block_sum(float v, float* sred) {
    int lane = threadIdx.x & 31, wid = threadIdx.x >> 5;
    #pragma unroll
    for (int o = 16; o; o >>= 1) v += __shfl_xor_sync(0xffffffffu, v, o);
    if (lane == 0) sred[wid] = v;
    __syncthreads();
    float t = 0.f;
    if (wid == 0) {
        t = (lane < NW) ? sred[lane] : 0.f;
        #pragma unroll
        for (int o = 8; o; o >>= 1) t += __shfl_xor_sync(0xffffffffu, t, o);
        if (lane == 0) sred[0] = t;
    }
    __syncthreads();
    float r = sred[0];
    __syncthreads();
    return r;
}

// ---------------- warp dot: NB8 batches of 1024 floats (R2 champion, untouched) ----------------
template<int NB8>
__device__ __forceinline__ float warp_dotN(const float* __restrict__ w,
                                           const float* __restrict__ vec) {
    const int lane = threadIdx.x & 31;
    const float4* __restrict__ w4 = reinterpret_cast<const float4*>(w);
    const float4* __restrict__ v4 = reinterpret_cast<const float4*>(vec);
    float ax = 0.f, ay = 0.f, az = 0.f, aw = 0.f;
    #pragma unroll
    for (int b = 0; b < NB8; b++) {
        float4 a[8];
        #pragma unroll
        for (int i = 0; i < 8; i++)
            a[i] = __ldg(w4 + b * 256 + i * 32 + lane);
        #pragma unroll
        for (int i = 0; i < 8; i++) {
            float4 bv = v4[b * 256 + i * 32 + lane];
            ax = fmaf(a[i].x, bv.x, ax);
            ay = fmaf(a[i].y, bv.y, ay);
            az = fmaf(a[i].z, bv.z, az);
            aw = fmaf(a[i].w, bv.w, aw);
        }
    }
    float acc = (ax + ay) + (az + aw);
    #pragma unroll
    for (int o = 16; o; o >>= 1) acc += __shfl_xor_sync(0xffffffffu, acc, o);
    return acc;
}

__global__ __launch_bounds__(NT, 1) void rwkv_persistent(
    const int*   __restrict__ ctx,
    const float* __restrict__ st_in,
    const float* __restrict__ emb,
    const float* __restrict__ ln0,
    const float* __restrict__ ln1,
    const float* __restrict__ ln2,
    const float* __restrict__ lnout,
    const float* __restrict__ tmk,
    const float* __restrict__ tmv,
    const float* __restrict__ tmr,
    const float* __restrict__ tfirst,
    const float* __restrict__ tdecay,
    const float* __restrict__ kw,
    const float* __restrict__ vw,
    const float* __restrict__ rw,
    const float* __restrict__ ow,
    const float* __restrict__ ftmk,
    const float* __restrict__ ftmr,
    const float* __restrict__ fkw,
    const float* __restrict__ fvw,
    const float* __restrict__ frw,
    const float* __restrict__ head,
    float* __restrict__ out,
    int nb)
{
    __shared__ float sbuf[4096];
    __shared__ float xprk[D];
    __shared__ float sred[NW];

    const int tid  = threadIdx.x;
    const int lane = tid & 31;
    const int bid  = blockIdx.x;
    const int gw   = bid * NW + (tid >> 5);
    const int nwG  = nb * NW;

    float* out_logits = out;
    float* out_state  = out + VOCAB;

    // ---------- stage 0: x = rms(emb[ctx[0]], ln0) into xb[0] ----------
    if (bid == 0) {
        const float* e = emb + (size_t)ctx[0] * D;
        float ss = 0.f;
        for (int j = tid; j < D; j += NT) { float t = e[j]; ss += t * t; }
        ss = block_sum(ss, sred);
        float inv = rsqrtf(ss * (1.f / D) + 1e-5f);
        for (int j = tid; j < D; j += NT) g_xb[0][j] = e[j] * inv * ln0[j];
    }
    grid_barrier(nb);

    for (int l = 0; l < LNUM; l++) {
        const int p = l & 1, np = p ^ 1;
        const float scp = (l > 0 && (l % 6 == 0)) ? 0.5f : 1.0f;  // prev layer rescale
        const float* st_l  = st_in     + (size_t)l * 5 * D;
        float*       ost_l = out_state + (size_t)l * 5 * D;

        // ---------- stage A: fold prev tail + rms + token-mix; k/v/r matvecs ----------
        {
            float ss = 0.f;
            for (int j = tid; j < D; j += NT) {
                float xv = g_xb[p][j];
                if (l > 0) {
                    float sr = 1.f / (1.f + __expf(-g_r2[j]));
                    xv = (xv + sr * g_accD[j]) * scp;
                }
                xprk[j] = xv;
                ss += xv * xv;
            }
            ss = block_sum(ss, sred);
            float inv = rsqrtf(ss * (1.f / D) + 1e-5f);
            const float* l1 = ln1 + l * D;
            const float* mk = tmk + l * D;
            const float* mv = tmv + l * D;
            const float* mr = tmr + l * D;
            for (int j = tid; j < D; j += NT) {
                float xv  = xprk[j];
                float xxj = xv * inv * l1[j];
                float sa  = st_l[D + j];
                float a_ = mk[j]; sbuf[j]         = xxj * a_ + sa * (1.f - a_);
                float b_ = mv[j]; sbuf[D + j]     = xxj * b_ + sa * (1.f - b_);
                float c_ = mr[j]; sbuf[2 * D + j] = xxj * c_ + sa * (1.f - c_);
                if (bid == 0) ost_l[D + j] = xxj;   // new sa_x
            }
            __syncthreads();
            // publish folded x into the other buffer (blocks 0,1 cover D once)
            if (bid < 2) g_xb[np][bid * NT + tid] = xprk[bid * NT + tid];
            const float* kwl = kw + (size_t)l * D * D;
            const float* vwl = vw + (size_t)l * D * D;
            const float* rwl = rw + (size_t)l * D * D;
            for (int row = gw; row < 3 * D; row += nwG) {
                float r;
                if (row < D) {
                    r = warp_dotN<1>(kwl + (size_t)row * D, sbuf);
                    if (lane == 0) g_k[row] = r;
                } else if (row < 2 * D) {
                    r = warp_dotN<1>(vwl + (size_t)(row - D) * D, sbuf + D);
                    if (lane == 0) g_v[row - D] = r;
                } else {
                    r = warp_dotN<1>(rwl + (size_t)(row - 2 * D) * D, sbuf + 2 * D);
                    if (lane == 0) g_r[row - 2 * D] = r;
                }
            }
        }
        grid_barrier(nb);

        // ---------- stage B: WKV elementwise; ow matvec into xb[np] ----------
        {
            const float* tfl = tfirst + l * D;
            const float* tdl = tdecay + l * D;
            for (int j = tid; j < D; j += NT) {
                float k  = g_k[j], v = g_v[j], rr = g_r[j];
                float aa = st_l[2 * D + j], bb = st_l[3 * D + j], pp = st_l[4 * D + j];
                float ww = tfl[j] + k;
                float pm = fmaxf(pp, ww);
                float e1 = __expf(pp - pm), e2 = __expf(ww - pm);
                float a  = e1 * aa + e2 * v;
                float b  = e1 * bb + e2;
                float sr = 1.f / (1.f + __expf(-rr));
                sbuf[j] = sr * (a / b);
                if (bid == 0) {
                    float ww2 = pp + tdl[j];
                    float p2  = fmaxf(ww2, k);
                    float e1b = __expf(ww2 - p2), e2b = __expf(k - p2);
                    ost_l[2 * D + j] = e1b * aa + e2b * v;  // naa
                    ost_l[3 * D + j] = e1b * bb + e2b;      // nbb
                    ost_l[4 * D + j] = p2;                  // pp
                }
            }
            __syncthreads();
            const float* owl = ow + (size_t)l * D * D;
            for (int row = gw; row < D; row += nwG) {
                float dv = warp_dotN<1>(owl + (size_t)row * D, sbuf);
                if (lane == 0) g_xb[np][row] += dv;
            }
        }
        grid_barrier(nb);

        // ---------- stage C: rms2 + channel-mix prep; fkw/frw; zero accD ----------
        {
            float ss = 0.f;
            for (int j = tid; j < D; j += NT) { float t = g_xb[np][j]; ss += t * t; }
            ss = block_sum(ss, sred);
            float inv = rsqrtf(ss * (1.f / D) + 1e-5f);
            const float* l2l = ln2  + l * D;
            const float* fmk = ftmk + l * D;
            const float* fmr = ftmr + l * D;
            for (int j = tid; j < D; j += NT) {
                float yyj = g_xb[np][j] * inv * l2l[j];
                float ff  = st_l[j];
                float a_ = fmk[j]; sbuf[j]     = yyj * a_ + ff * (1.f - a_);
                float b_ = fmr[j]; sbuf[D + j] = yyj * b_ + ff * (1.f - b_);
                if (bid == 0) ost_l[j] = yyj;   // new ff_x
            }
            if (bid >= 2 && bid < 4) g_accD[(bid - 2) * NT + tid] = 0.f;
            __syncthreads();
            const float* fkwl = fkw + (size_t)l * HD * D;
            const float* frwl = frw + (size_t)l * D * D;
            for (int row = gw; row < HD + D; row += nwG) {
                if (row < HD) {
                    float t = warp_dotN<1>(fkwl + (size_t)row * D, sbuf);
                    if (lane == 0) { t = fmaxf(t, 0.f); g_k2[row] = t * t; }
                } else {
                    float t = warp_dotN<1>(frwl + (size_t)(row - HD) * D, sbuf + D);
                    if (lane == 0) g_r2[row - HD] = t;
                }
            }
        }
        grid_barrier(nb);

        // ---------- stage D: fvw split into 4096 x 4KB tasks -> accD ----------
        {
            for (int j = tid; j < HD; j += NT) sbuf[j] = g_k2[j];
            __syncthreads();
            const float* fvwl = fvw + (size_t)l * D * HD;
            for (int t = gw; t < 4 * D; t += nwG) {
                int row = t >> 2, c = t & 3;
                float pt = warp_dotN<1>(fvwl + (size_t)row * HD + (size_t)c * 1024,
                                        sbuf + c * 1024);
                if (lane == 0) atomicAdd(&g_accD[row], pt);
            }
        }
        grid_barrier(nb);
    }

    // ---------- head: fold layer-11 tail, rms, logits ----------
    {
        const int pf = LNUM & 1;           // buffer holding x after stage B of layer 11
        const float scp = (LNUM % 6 == 0) ? 0.5f : 1.0f;
        float ss = 0.f;
        for (int j = tid; j < D; j += NT) {
            float sr = 1.f / (1.f + __expf(-g_r2[j]));
            float xv = (g_xb[pf][j] + sr * g_accD[j]) * scp;
            xprk[j] = xv;
            ss += xv * xv;
        }
        ss = block_sum(ss, sred);
        float inv = rsqrtf(ss * (1.f / D) + 1e-5f);
        for (int j = tid; j < D; j += NT) sbuf[j] = xprk[j] * inv * lnout[j];
        __syncthreads();
        for (int row = gw; row < VOCAB; row += nwG) {
            float t = warp_dotN<1>(head + (size_t)row * D, sbuf);
            if (lane == 0) out_logits[row] = t;
        }
    }
}

extern "C" void kernel_launch(void* const* d_in, const int* in_sizes, int n_in,
                              void* d_out, int out_size) {
    (void)in_sizes; (void)n_in; (void)out_size;
    int nb = 0;
    cudaDeviceGetAttribute(&nb, cudaDevAttrMultiProcessorCount, 0);
    if (nb <= 0) nb = 148;
    if (nb > 1024) nb = 1024;

    rwkv_persistent<<<nb, NT>>>(
        (const int*)  d_in[0],   // ctx
        (const float*)d_in[1],   // state
        (const float*)d_in[2],   // emb
        (const float*)d_in[3],   // ln0_w
        (const float*)d_in[4],   // ln1_w
        (const float*)d_in[5],   // ln2_w
        (const float*)d_in[6],   // lnout_w
        (const float*)d_in[7],   // att_tmk
        (const float*)d_in[8],   // att_tmv
        (const float*)d_in[9],   // att_tmr
        (const float*)d_in[10],  // att_tfirst
        (const float*)d_in[11],  // att_tdecay
        (const float*)d_in[12],  // att_kw
        (const float*)d_in[13],  // att_vw
        (const float*)d_in[14],  // att_rw
        (const float*)d_in[15],  // att_ow
        (const float*)d_in[16],  // ffn_tmk
        (const float*)d_in[17],  // ffn_tmr
        (const float*)d_in[18],  // ffn_kw
        (const float*)d_in[19],  // ffn_vw
        (const float*)d_in[20],  // ffn_rw
        (const float*)d_in[21],  // head
        (float*)d_out, nb);
}